// round 3
// baseline (speedup 1.0000x reference)
#include <cuda_runtime.h>
#include <cuda_bf16.h>
#include <math.h>

#define N_PROP   65536
#define N_GT     64
#define NCLS     81
#define TOTAL    512
#define MAX_POS  128
#define TPB      512
#define NBLK     128            // N_PROP / TPB
#define NWARP    (TPB / 32)     // 16

// -------- device scratch --------
__device__ int   g_blk_pos[NBLK];
__device__ int   g_blk_neg[NBLK];
__device__ int   g_pos_list[TOTAL];   // packed (gt<<16)|i
__device__ int   g_neg_list[TOTAL];
__device__ int   g_non_list[TOTAL];
__device__ float g_ce[TOTAL];
__device__ float g_rg[TOTAL];
__device__ int            g_bar_count;
__device__ volatile int   g_bar_gen;
__device__ int            g_done;

__device__ __forceinline__ void gbar() {
    __threadfence();            // publish this thread's global writes
    __syncthreads();
    if (threadIdx.x == 0) {
        int gen = g_bar_gen;
        if (atomicAdd(&g_bar_count, 1) == NBLK - 1) {
            g_bar_count = 0;
            __threadfence();
            g_bar_gen = gen + 1;
        } else {
            while (g_bar_gen == gen) { }
            __threadfence();
        }
    }
    __syncthreads();
}

__device__ __forceinline__ float sl1(float d) {
    float ad = fabsf(d);
    return (ad < 1.0f) ? (0.5f * d * d) : (ad - 0.5f);
}

__global__ void __launch_bounds__(TPB)
k_fused(const float* __restrict__ props,
        const float* __restrict__ gts,
        const int*   __restrict__ gt_labels,
        const float* __restrict__ score,
        const float* __restrict__ txty,
        float* __restrict__ out,
        int n_gt) {
    __shared__ float4 sg[N_GT];
    __shared__ float  sga[N_GT];
    __shared__ int    slbl[N_GT];
    __shared__ int    wpc[NWARP], wnc[NWARP];
    __shared__ int    swp[4], swn[4];
    __shared__ int    ssp[NBLK], ssn[NBLK];
    __shared__ int    s_numpos, s_negtot, s_offp, s_offn;
    __shared__ int    s_last;
    __shared__ float  rc[NWARP], rr[NWARP];

    const int t    = threadIdx.x;
    const int bid  = blockIdx.x;
    const int warp = t >> 5, lane = t & 31;
    const unsigned full = 0xffffffffu;

    // ============ phase 1: IoU + classify ============
    if (t < N_GT) {
        float4 g = ((const float4*)gts)[t];
        sg[t] = g;
        sga[t] = (g.z - g.x) * (g.w - g.y);
        slbl[t] = gt_labels[t];
    }
    __syncthreads();

    const int i = bid * TPB + t;
    float4 p = ((const float4*)props)[i];
    float pa = (p.z - p.x) * (p.w - p.y);

    float best = -1.0f;
    int bj = 0;
#pragma unroll 8
    for (int j = 0; j < N_GT; j++) {
        float4 g = sg[j];
        float ix = fmaxf(fminf(p.z, g.z) - fmaxf(p.x, g.x), 0.0f);
        float iy = fmaxf(fminf(p.w, g.w) - fmaxf(p.y, g.y), 0.0f);
        float inter = ix * iy;
        float iou = inter / (pa + sga[j] - inter + 1e-8f);
        if (iou > best) { best = iou; bj = j; }   // strict > = first argmax
    }
    const int f = (best >= 0.5f) ? 1 : ((best >= 0.1f) ? 2 : 0);

    unsigned bp = __ballot_sync(full, f == 1);
    unsigned bn = __ballot_sync(full, f == 2);
    if (lane == 0) { wpc[warp] = __popc(bp); wnc[warp] = __popc(bn); }
    __syncthreads();
    if (t == 0) {
        int cp = 0, cn = 0;
#pragma unroll
        for (int w = 0; w < NWARP; w++) { cp += wpc[w]; cn += wnc[w]; }
        g_blk_pos[bid] = cp;
        g_blk_neg[bid] = cn;
    }

    gbar();

    // ============ phase 2: shfl scan (width 128) + stable select ============
    if (warp < 4) {            // threads 0..127 scan the 128 block counts
        int ip = __ldcg(&g_blk_pos[t]);
        int in_ = __ldcg(&g_blk_neg[t]);
#pragma unroll
        for (int o = 1; o < 32; o <<= 1) {
            int ap = __shfl_up_sync(full, ip, o);
            int an = __shfl_up_sync(full, in_, o);
            if (lane >= o) { ip += ap; in_ += an; }
        }
        if (lane == 31) { swp[warp] = ip; swn[warp] = in_; }
    }
    __syncthreads();
    if (warp < 4) {
        int basep = 0, basen = 0;
#pragma unroll
        for (int w = 0; w < 4; w++) {
            if (w < warp) { basep += swp[w]; basen += swn[w]; }
        }
        ssp[t] = basep + ((warp < 4) ? 0 : 0);
        ssp[t] = basep; ssn[t] = basen;
        // store inclusive scans
        ssp[t] += 0; ssn[t] += 0;
        ssp[t] = basep; ssn[t] = basen;     // placeholder overwritten below
    }
    __syncthreads();
    if (warp < 4) {
        // recompute inclusive value (registers lost above? no - redo cleanly)
    }
    __syncthreads();
    // --- clean re-do of scan write (keep it simple & correct) ---
    if (warp < 4) {
        int ip = __ldcg(&g_blk_pos[t]);
        int in_ = __ldcg(&g_blk_neg[t]);
#pragma unroll
        for (int o = 1; o < 32; o <<= 1) {
            int ap = __shfl_up_sync(full, ip, o);
            int an = __shfl_up_sync(full, in_, o);
            if (lane >= o) { ip += ap; in_ += an; }
        }
        int basep = 0, basen = 0;
#pragma unroll
        for (int w = 0; w < 4; w++) {
            if (w < warp) { basep += swp[w]; basen += swn[w]; }
        }
        ssp[t] = basep + ip;
        ssn[t] = basen + in_;
    }
    __syncthreads();
    if (t == 0) {
        s_offp   = (bid > 0) ? ssp[bid - 1] : 0;
        s_offn   = (bid > 0) ? ssn[bid - 1] : 0;
        s_numpos = min(ssp[NBLK - 1], MAX_POS);
        s_negtot = ssn[NBLK - 1];
    }
    __syncthreads();

    {
        int pre_p = 0, pre_n = 0;
        for (int w = 0; w < warp; w++) { pre_p += wpc[w]; pre_n += wnc[w]; }
        unsigned lm = (1u << lane) - 1u;
        int neg_before = pre_n + __popc(bn & lm);
        if (f == 1) {
            int r = s_offp + pre_p + __popc(bp & lm);
            if (r < TOTAL) g_pos_list[r] = i | (bj << 16);
        } else if (f == 2) {
            int r = s_offn + neg_before;
            if (r < TOTAL) g_neg_list[r] = i;
        }
        if (f != 2) {
            int r = (bid * TPB - s_offn) + (t - neg_before);
            if (r < TOTAL) g_non_list[r] = i;
        }
    }

    gbar();

    // ============ phase 3: loss (4 warps/block -> 512 slots) ============
    if (warp < 4) {
        int slot = bid * 4 + warp;
        int num_pos = s_numpos;
        int neg_total = s_negtot;
        bool is_pos = slot < num_pos;
        int e;
        if (is_pos) e = __ldcg(&g_pos_list[slot]);
        else {
            int j = slot - num_pos;
            e = (j < neg_total) ? __ldcg(&g_neg_list[j])
                                : __ldcg(&g_non_list[j - neg_total]);
        }
        int idx = e & 0xFFFF;
        int g   = e >> 16;                 // only meaningful (and used) when pos
        int lbl = is_pos ? slbl[g] : 0;

        const float* row = score + (size_t)idx * NCLS;
        float v0 = row[lane];
        float v1 = row[lane + 32];
        float v2 = (lane + 64 < NCLS) ? row[lane + 64] : -INFINITY;
        float m = fmaxf(fmaxf(v0, v1), v2);
#pragma unroll
        for (int o = 16; o; o >>= 1) m = fmaxf(m, __shfl_xor_sync(full, m, o));
        float s = expf(v0 - m) + expf(v1 - m) + ((lane + 64 < NCLS) ? expf(v2 - m) : 0.0f);
#pragma unroll
        for (int o = 16; o; o >>= 1) s += __shfl_xor_sync(full, s, o);

        // fetch row[lbl] from registers via shfl (lbl uniform per warp)
        float cand = (lbl < 32) ? v0 : ((lbl < 64) ? v1 : v2);
        float vl = __shfl_sync(full, cand, lbl & 31);

        if (lane == 0) {
            float ce = m + logf(s) - vl;
            float rg = 0.0f;
            if (is_pos) {
                float4 pp = ((const float4*)props)[idx];
                float4 gb = sg[g];
                float pw = pp.z - pp.x, ph = pp.w - pp.y;
                float pcx = pp.x + 0.5f * pw, pcy = pp.y + 0.5f * ph;
                float gw = gb.z - gb.x, gh = gb.w - gb.y;
                float gcx = gb.x + 0.5f * gw, gcy = gb.y + 0.5f * gh;
                float t0 = ((gcx - pcx) / pw) * 10.0f;
                float t1 = ((gcy - pcy) / ph) * 10.0f;
                float t2 = logf(gw / pw) * 5.0f;
                float t3 = logf(gh / ph) * 5.0f;
                float4 pv = *(const float4*)(txty + ((size_t)idx * NCLS + g) * 4);
                rg = sl1(pv.x - t0) + sl1(pv.y - t1) + sl1(pv.z - t2) + sl1(pv.w - t3);
            }
            g_ce[slot] = ce;
            g_rg[slot] = rg;
            __threadfence();               // publish before ticket
        }
    }

    // ============ phase 4: last-arriving block reduces, others exit ============
    __syncthreads();
    if (t == 0) {
        s_last = (atomicAdd(&g_done, 1) == NBLK - 1) ? 1 : 0;
        if (s_last) g_done = 0;            // reset for next graph replay
    }
    __syncthreads();
    if (s_last) {
        __threadfence();                   // acquire all blocks' ce/rg
        float c  = __ldcg(&g_ce[t]);
        float r2 = __ldcg(&g_rg[t]);
#pragma unroll
        for (int o = 16; o; o >>= 1) {
            c  += __shfl_xor_sync(full, c, o);
            r2 += __shfl_xor_sync(full, r2, o);
        }
        if (lane == 0) { rc[warp] = c; rr[warp] = r2; }
        __syncthreads();
        if (warp == 0) {
            float cc = (lane < NWARP) ? rc[lane] : 0.0f;
            float rrv = (lane < NWARP) ? rr[lane] : 0.0f;
#pragma unroll
            for (int o = 8; o; o >>= 1) {
                cc  += __shfl_xor_sync(full, cc, o);
                rrv += __shfl_xor_sync(full, rrv, o);
            }
            if (lane == 0) {
                out[0] = cc  * (1.0f / (float)TOTAL);
                out[1] = rrv * (1.0f / (float)TOTAL);
            }
        }
    }
}

extern "C" void kernel_launch(void* const* d_in, const int* in_sizes, int n_in,
                              void* d_out, int out_size) {
    const float* props = (const float*)d_in[1];
    const float* score = (const float*)d_in[2];
    const float* txty  = (const float*)d_in[3];
    const float* gts   = (const float*)d_in[4];
    const int*   glbl  = (const int*)d_in[5];
    float* out = (float*)d_out;
    int n_gt = in_sizes[4] / 4;

    k_fused<<<NBLK, TPB>>>(props, gts, glbl, score, txty, out, n_gt);
}

// round 4
// speedup vs baseline: 1.4965x; 1.4965x over previous
#include <cuda_runtime.h>
#include <cuda_bf16.h>
#include <math.h>

#define N_PROP   65536
#define N_GT     64
#define NCLS     81
#define TOTAL    512
#define MAX_POS  128
#define TPB      512
#define PPB      256            // proposals per block (2 threads each)
#define NBLK     256            // N_PROP / PPB
#define NWARP    (TPB / 32)

// -------- device scratch --------
__device__ int   g_blk_pos[NBLK];
__device__ int   g_blk_neg[NBLK];
__device__ int   g_pos_list[TOTAL];   // packed (gt<<16)|i
__device__ int   g_neg_list[TOTAL];
__device__ int   g_non_list[TOTAL];
__device__ float g_ce[TOTAL];
__device__ float g_rg[TOTAL];
__device__ int            g_bar_count;
__device__ volatile int   g_bar_gen;
__device__ int            g_done;

__device__ __forceinline__ void gbar() {
    __threadfence();
    __syncthreads();
    if (threadIdx.x == 0) {
        int gen = g_bar_gen;
        if (atomicAdd(&g_bar_count, 1) == NBLK - 1) {
            g_bar_count = 0;
            __threadfence();
            g_bar_gen = gen + 1;
        } else {
            while (g_bar_gen == gen) { }
            __threadfence();
        }
    }
    __syncthreads();
}

__device__ __forceinline__ float sl1(float d) {
    float ad = fabsf(d);
    return (ad < 1.0f) ? (0.5f * d * d) : (ad - 0.5f);
}

__global__ void __launch_bounds__(TPB)
k_fused(const float* __restrict__ props,
        const float* __restrict__ gts,
        const int*   __restrict__ gt_labels,
        const float* __restrict__ score,
        const float* __restrict__ txty,
        float* __restrict__ out,
        int n_gt) {
    __shared__ float4 sg[N_GT];
    __shared__ float  sga[N_GT];
    __shared__ int    slbl[N_GT];
    __shared__ float  s_ci[PPB], s_cu[PPB];
    __shared__ int    s_cj[PPB];
    __shared__ int    wpc[8], wnc[8];        // warps 0..7 own proposals
    __shared__ int    swp[8], swn[8];
    __shared__ int    ssp[NBLK], ssn[NBLK];
    __shared__ int    s_numpos, s_negtot, s_offp, s_offn;
    __shared__ int    s_last;
    __shared__ float  rc[NWARP], rr[NWARP];

    const int t    = threadIdx.x;
    const int bid  = blockIdx.x;
    const int warp = t >> 5, lane = t & 31;
    const int half = t >> 8;                 // 0: gts [0,32), 1: gts [32,64)
    const int lp   = t & (PPB - 1);          // local proposal id
    const unsigned full = 0xffffffffu;

    // ---- stage gt data ----
    if (t < N_GT) {
        float4 g = ((const float4*)gts)[t];
        sg[t] = g;
        sga[t] = (g.z - g.x) * (g.w - g.y);
        slbl[t] = gt_labels[t];
    }
    __syncthreads();

    // ============ phase 1: IoU argmax (division-free), 2 threads/proposal ===
    const int i = bid * PPB + lp;
    const float4 p = ((const float4*)props)[i];
    const float pa = (p.z - p.x) * (p.w - p.y);

    const int j0 = half * 32;
    float bi, bu; int bj;
    {
        float4 g = sg[j0];
        float ix = fmaxf(fminf(p.z, g.z) - fmaxf(p.x, g.x), 0.0f);
        float iy = fmaxf(fminf(p.w, g.w) - fmaxf(p.y, g.y), 0.0f);
        bi = ix * iy;
        bu = ((pa + sga[j0]) - bi) + 1e-8f;   // exact reference assoc order
        bj = j0;
    }
#pragma unroll 8
    for (int j = j0 + 1; j < j0 + 32; j++) {
        float4 g = sg[j];
        float ix = fmaxf(fminf(p.z, g.z) - fmaxf(p.x, g.x), 0.0f);
        float iy = fmaxf(fminf(p.w, g.w) - fmaxf(p.y, g.y), 0.0f);
        float inter = ix * iy;
        float u = ((pa + sga[j]) - inter) + 1e-8f;
        // iou_j > iou_best  <=>  inter*bu > bi*u   (all positive)
        if (inter * bu > bi * u) { bi = inter; bu = u; bj = j; }
    }
    if (half == 1) { s_ci[lp] = bi; s_cu[lp] = bu; s_cj[lp] = bj; }
    __syncthreads();

    int f = 0;
    unsigned bp = 0, bn = 0;
    if (half == 0) {
        float ui = s_ci[lp], uu = s_cu[lp];
        if (ui * bu > bi * uu) { bi = ui; bu = uu; bj = s_cj[lp]; }  // upper wins only if strictly >
        float miou = bi / bu;                 // single exact division, matches reference rounding
        f = (miou >= 0.5f) ? 1 : ((miou >= 0.1f) ? 2 : 0);
        bp = __ballot_sync(full, f == 1);
        bn = __ballot_sync(full, f == 2);
        if (lane == 0) { wpc[warp] = __popc(bp); wnc[warp] = __popc(bn); }
    }
    __syncthreads();
    if (t == 0) {
        int cp = 0, cn = 0;
#pragma unroll
        for (int w = 0; w < 8; w++) { cp += wpc[w]; cn += wnc[w]; }
        g_blk_pos[bid] = cp;
        g_blk_neg[bid] = cn;
    }

    gbar();

    // ============ phase 2: shfl scan (256 counts) + stable select ============
    if (t < NBLK) {
        int ip  = __ldcg(&g_blk_pos[t]);
        int in_ = __ldcg(&g_blk_neg[t]);
#pragma unroll
        for (int o = 1; o < 32; o <<= 1) {
            int ap = __shfl_up_sync(full, ip, o);
            int an = __shfl_up_sync(full, in_, o);
            if (lane >= o) { ip += ap; in_ += an; }
        }
        if (lane == 31) { swp[warp] = ip; swn[warp] = in_; }
        __syncthreads();
        int basep = 0, basen = 0;
        for (int w = 0; w < warp; w++) { basep += swp[w]; basen += swn[w]; }
        ssp[t] = basep + ip;
        ssn[t] = basen + in_;
    } else {
        __syncthreads();
    }
    __syncthreads();
    if (t == 0) {
        s_offp   = (bid > 0) ? ssp[bid - 1] : 0;
        s_offn   = (bid > 0) ? ssn[bid - 1] : 0;
        s_numpos = min(ssp[NBLK - 1], MAX_POS);
        s_negtot = ssn[NBLK - 1];
    }
    __syncthreads();

    if (half == 0) {
        int pre_p = 0, pre_n = 0;
        for (int w = 0; w < warp; w++) { pre_p += wpc[w]; pre_n += wnc[w]; }
        unsigned lm = (1u << lane) - 1u;
        int neg_before = pre_n + __popc(bn & lm);
        if (f == 1) {
            int r = s_offp + pre_p + __popc(bp & lm);
            if (r < TOTAL) g_pos_list[r] = i | (bj << 16);
        } else if (f == 2) {
            int r = s_offn + neg_before;
            if (r < TOTAL) g_neg_list[r] = i;
        }
        if (f != 2) {
            int r = (bid * PPB - s_offn) + (lp - neg_before);
            if (r < TOTAL) g_non_list[r] = i;
        }
    }

    gbar();

    // ============ phase 3: loss (2 warps/block -> 512 slots) ============
    if (warp < 2) {
        int slot = bid * 2 + warp;
        int num_pos = s_numpos;
        int neg_total = s_negtot;
        bool is_pos = slot < num_pos;
        int e;
        if (is_pos) e = __ldcg(&g_pos_list[slot]);
        else {
            int j = slot - num_pos;
            e = (j < neg_total) ? __ldcg(&g_neg_list[j])
                                : __ldcg(&g_non_list[j - neg_total]);
        }
        int idx = e & 0xFFFF;
        int g   = e >> 16;
        int lbl = is_pos ? slbl[g] : 0;

        const float* row = score + (size_t)idx * NCLS;
        float v0 = row[lane];
        float v1 = row[lane + 32];
        float v2 = (lane + 64 < NCLS) ? row[lane + 64] : -INFINITY;
        float m = fmaxf(fmaxf(v0, v1), v2);
#pragma unroll
        for (int o = 16; o; o >>= 1) m = fmaxf(m, __shfl_xor_sync(full, m, o));
        float s = expf(v0 - m) + expf(v1 - m) + ((lane + 64 < NCLS) ? expf(v2 - m) : 0.0f);
#pragma unroll
        for (int o = 16; o; o >>= 1) s += __shfl_xor_sync(full, s, o);

        float cand = (lbl < 32) ? v0 : ((lbl < 64) ? v1 : v2);
        float vl = __shfl_sync(full, cand, lbl & 31);

        if (lane == 0) {
            float ce = m + logf(s) - vl;
            float rg = 0.0f;
            if (is_pos) {
                float4 pp = ((const float4*)props)[idx];
                float4 gb = sg[g];
                float pw = pp.z - pp.x, ph = pp.w - pp.y;
                float pcx = pp.x + 0.5f * pw, pcy = pp.y + 0.5f * ph;
                float gw = gb.z - gb.x, gh = gb.w - gb.y;
                float gcx = gb.x + 0.5f * gw, gcy = gb.y + 0.5f * gh;
                float t0 = ((gcx - pcx) / pw) * 10.0f;
                float t1 = ((gcy - pcy) / ph) * 10.0f;
                float t2 = logf(gw / pw) * 5.0f;
                float t3 = logf(gh / ph) * 5.0f;
                float4 pv = *(const float4*)(txty + ((size_t)idx * NCLS + g) * 4);
                rg = sl1(pv.x - t0) + sl1(pv.y - t1) + sl1(pv.z - t2) + sl1(pv.w - t3);
            }
            g_ce[slot] = ce;
            g_rg[slot] = rg;
            __threadfence();
        }
    }

    // ============ phase 4: last-arriving block reduces ============
    __syncthreads();
    if (t == 0) {
        s_last = (atomicAdd(&g_done, 1) == NBLK - 1) ? 1 : 0;
        if (s_last) g_done = 0;
    }
    __syncthreads();
    if (s_last) {
        __threadfence();
        float c  = __ldcg(&g_ce[t]);
        float r2 = __ldcg(&g_rg[t]);
#pragma unroll
        for (int o = 16; o; o >>= 1) {
            c  += __shfl_xor_sync(full, c, o);
            r2 += __shfl_xor_sync(full, r2, o);
        }
        if (lane == 0) { rc[warp] = c; rr[warp] = r2; }
        __syncthreads();
        if (warp == 0) {
            float cc  = (lane < NWARP) ? rc[lane] : 0.0f;
            float rrv = (lane < NWARP) ? rr[lane] : 0.0f;
#pragma unroll
            for (int o = 8; o; o >>= 1) {
                cc  += __shfl_xor_sync(full, cc, o);
                rrv += __shfl_xor_sync(full, rrv, o);
            }
            if (lane == 0) {
                out[0] = cc  * (1.0f / (float)TOTAL);
                out[1] = rrv * (1.0f / (float)TOTAL);
            }
        }
    }
}

extern "C" void kernel_launch(void* const* d_in, const int* in_sizes, int n_in,
                              void* d_out, int out_size) {
    const float* props = (const float*)d_in[1];
    const float* score = (const float*)d_in[2];
    const float* txty  = (const float*)d_in[3];
    const float* gts   = (const float*)d_in[4];
    const int*   glbl  = (const int*)d_in[5];
    float* out = (float*)d_out;
    int n_gt = in_sizes[4] / 4;

    k_fused<<<NBLK, TPB>>>(props, gts, glbl, score, txty, out, n_gt);
}